// round 2
// baseline (speedup 1.0000x reference)
#include <cuda_runtime.h>
#include <math.h>

// Problem constants
#define SEQ     4096
#define HIDDEN  1024
#define NH      16
#define HD      64
#define NB      16
#define BLK     256
#define BATCH   2
#define MROWS   (BATCH * SEQ)   // 8192

// Scratch for Q, K, V in [B, S, nh, d] layout == [MROWS, 1024] row-major
__device__ float g_Q[MROWS * HIDDEN];
__device__ float g_K[MROWS * HIDDEN];
__device__ float g_V[MROWS * HIDDEN];

// ---------------------------------------------------------------------------
// QKV projection GEMM: Out[m, n] = sum_k X[m, k] * W[k, n] + Bias[n]
// M = 8192, N = 1024, K = 1024. blockIdx.z selects q / k / v.
// 128x128x16 tiles, 256 threads, 8x8 per-thread microtile, double-buffered.
// ---------------------------------------------------------------------------
__global__ __launch_bounds__(256) void qkv_gemm(
    const float* __restrict__ X,
    const float* __restrict__ Wq, const float* __restrict__ Bq,
    const float* __restrict__ Wk, const float* __restrict__ Bk,
    const float* __restrict__ Wv, const float* __restrict__ Bv)
{
    const float* W;
    const float* Bias;
    float* Out;
    if (blockIdx.z == 0)      { W = Wq; Bias = Bq; Out = g_Q; }
    else if (blockIdx.z == 1) { W = Wk; Bias = Bk; Out = g_K; }
    else                      { W = Wv; Bias = Bv; Out = g_V; }

    const int m0 = blockIdx.y * 128;
    const int n0 = blockIdx.x * 128;

    __shared__ float As[2][16][132];   // [k][m], padded pitch for store conflicts
    __shared__ float Bs[2][16][128];   // [k][n]
    __shared__ float sB[128];

    const int t  = threadIdx.x;
    const int tx = t & 15;             // 0..15 -> n microtile
    const int ty = t >> 4;             // 0..15 -> m microtile

    if (t < 128) sB[t] = Bias[n0 + t];

    // A loader: thread loads 2 float4 (rows ar, ar+64; k-chunk af*4)
    const int af = t & 3;
    const int ar = t >> 2;             // 0..63
    // B loader: thread loads 2 float4 (k rows br, br+8; n-chunk bf*4)
    const int bf = t & 31;
    const int br = t >> 5;             // 0..7

    auto loadA = [&](int buf, int k0) {
        #pragma unroll
        for (int rr = 0; rr < 2; rr++) {
            int row = ar + rr * 64;
            float4 v = *(const float4*)&X[(m0 + row) * 1024 + k0 + af * 4];
            As[buf][af * 4 + 0][row] = v.x;
            As[buf][af * 4 + 1][row] = v.y;
            As[buf][af * 4 + 2][row] = v.z;
            As[buf][af * 4 + 3][row] = v.w;
        }
    };
    auto loadB = [&](int buf, int k0) {
        #pragma unroll
        for (int rr = 0; rr < 2; rr++) {
            int kk = br + rr * 8;
            float4 v = *(const float4*)&W[(k0 + kk) * 1024 + n0 + bf * 4];
            *(float4*)&Bs[buf][kk][bf * 4] = v;
        }
    };

    loadA(0, 0);
    loadB(0, 0);
    __syncthreads();

    float acc[8][8];
    #pragma unroll
    for (int i = 0; i < 8; i++)
        #pragma unroll
        for (int j = 0; j < 8; j++)
            acc[i][j] = 0.0f;

    for (int k0 = 0; k0 < 1024; k0 += 16) {
        const int buf  = (k0 >> 4) & 1;
        const int nbuf = buf ^ 1;
        if (k0 + 16 < 1024) {
            loadA(nbuf, k0 + 16);
            loadB(nbuf, k0 + 16);
        }
        #pragma unroll
        for (int k = 0; k < 16; k++) {
            float a_frag[8], b_frag[8];
            *(float4*)&a_frag[0] = *(float4*)&As[buf][k][ty * 4];
            *(float4*)&a_frag[4] = *(float4*)&As[buf][k][64 + ty * 4];
            *(float4*)&b_frag[0] = *(float4*)&Bs[buf][k][tx * 4];
            *(float4*)&b_frag[4] = *(float4*)&Bs[buf][k][64 + tx * 4];
            #pragma unroll
            for (int i = 0; i < 8; i++)
                #pragma unroll
                for (int j = 0; j < 8; j++)
                    acc[i][j] = fmaf(a_frag[i], b_frag[j], acc[i][j]);
        }
        __syncthreads();
    }

    // Epilogue: add bias, write float4s
    #pragma unroll
    for (int ih = 0; ih < 2; ih++) {
        #pragma unroll
        for (int i = 0; i < 4; i++) {
            int row = m0 + ih * 64 + ty * 4 + i;
            #pragma unroll
            for (int jh = 0; jh < 2; jh++) {
                int cb = jh * 64 + tx * 4;
                float4 v;
                v.x = acc[ih * 4 + i][jh * 4 + 0] + sB[cb + 0];
                v.y = acc[ih * 4 + i][jh * 4 + 1] + sB[cb + 1];
                v.z = acc[ih * 4 + i][jh * 4 + 2] + sB[cb + 2];
                v.w = acc[ih * 4 + i][jh * 4 + 3] + sB[cb + 3];
                *(float4*)&Out[row * 1024 + n0 + cb] = v;
            }
        }
    }
}

// ---------------------------------------------------------------------------
// Block-local attention with permuted K/V source groups.
// CTA = (q-tile of 64 rows, group g = block*16+head, batch b).
// smem: qs[64][64], ks[256][64], vs[256][64] (ks/vs XOR-swizzled).
// Thread layout: rs = t>>4 (4 q-rows rs*4..), cs = t&15 (16 cols cs*16+j).
// ---------------------------------------------------------------------------
__global__ __launch_bounds__(256) void attn_kernel(
    const int* __restrict__ perm,
    float* __restrict__ out)
{
    extern __shared__ float sm[];
    float* qs = sm;                 // 64 * 64
    float* ks = sm + 64 * 64;       // 256 * 64 (swizzled)
    float* vs = ks + 256 * 64;      // 256 * 64 (swizzled)

    const int qt   = blockIdx.x;        // 0..3
    const int g    = blockIdx.y;        // 0..255
    const int b    = blockIdx.z;        // 0..1
    const int blk  = g >> 4;
    const int head = g & 15;
    const int src  = perm[g];
    const int sblk = src >> 4;
    const int shead = src & 15;

    const int t  = threadIdx.x;
    const int rs = t >> 4;              // 0..15
    const int cs = t & 15;              // 0..15
    const int r0 = rs * 4;

    // ---- load q tile (no swizzle) ----
    {
        const int base_s = blk * 256 + qt * 64;
        #pragma unroll
        for (int i = t; i < 64 * 16; i += 256) {
            int r = i >> 4, f4 = i & 15;
            float4 v = *(const float4*)&g_Q[((b * 4096 + base_s + r) * 16 + head) * 64 + f4 * 4];
            *(float4*)&qs[r * 64 + f4 * 4] = v;
        }
    }
    // ---- load K and V tiles from permuted source group, XOR swizzle ----
    {
        const int base_s = sblk * 256;
        #pragma unroll
        for (int i = t; i < 256 * 16; i += 256) {
            int c = i >> 4, f4 = i & 15;
            int f4s = (f4 ^ (c >> 4)) & 15;
            int gidx = ((b * 4096 + base_s + c) * 16 + shead) * 64 + f4 * 4;
            float4 kv = *(const float4*)&g_K[gidx];
            *(float4*)&ks[c * 64 + f4s * 4] = kv;
            float4 vv = *(const float4*)&g_V[gidx];
            *(float4*)&vs[c * 64 + f4s * 4] = vv;
        }
    }
    __syncthreads();

    // ---- logits: acc[i][j] = q[r0+i] . k[cs*16+j] ----
    float acc[4][16];
    #pragma unroll
    for (int i = 0; i < 4; i++)
        #pragma unroll
        for (int j = 0; j < 16; j++)
            acc[i][j] = 0.0f;

    for (int d = 0; d < 64; d += 4) {
        float4 q4[4];
        #pragma unroll
        for (int i = 0; i < 4; i++)
            q4[i] = *(float4*)&qs[(r0 + i) * 64 + d];
        const int d4s = ((d >> 2) ^ cs) & 15;
        #pragma unroll
        for (int j = 0; j < 16; j++) {
            const int c = cs * 16 + j;
            float4 kv = *(float4*)&ks[c * 64 + d4s * 4];
            #pragma unroll
            for (int i = 0; i < 4; i++) {
                acc[i][j] = fmaf(q4[i].x, kv.x, acc[i][j]);
                acc[i][j] = fmaf(q4[i].y, kv.y, acc[i][j]);
                acc[i][j] = fmaf(q4[i].z, kv.z, acc[i][j]);
                acc[i][j] = fmaf(q4[i].w, kv.w, acc[i][j]);
            }
        }
    }

    // ---- softmax over each row (scale = 1/8), 16-lane shuffle reductions ----
    const float scale = 0.125f;
    #pragma unroll
    for (int i = 0; i < 4; i++) {
        float m = acc[i][0];
        #pragma unroll
        for (int j = 1; j < 16; j++) m = fmaxf(m, acc[i][j]);
        #pragma unroll
        for (int o = 8; o >= 1; o >>= 1)
            m = fmaxf(m, __shfl_xor_sync(0xffffffffu, m, o, 16));
        float s = 0.0f;
        #pragma unroll
        for (int j = 0; j < 16; j++) {
            acc[i][j] = __expf(scale * (acc[i][j] - m));
            s += acc[i][j];
        }
        #pragma unroll
        for (int o = 8; o >= 1; o >>= 1)
            s += __shfl_xor_sync(0xffffffffu, s, o, 16);
        float is = 1.0f / s;
        #pragma unroll
        for (int j = 0; j < 16; j++) acc[i][j] *= is;
    }

    // ---- ctx = P @ V ; d split into 4 chunks of 16 ----
    const int s_base = blk * 256 + qt * 64 + r0;
    #pragma unroll
    for (int ch = 0; ch < 4; ch++) {
        float part[4][16];
        #pragma unroll
        for (int i = 0; i < 4; i++)
            #pragma unroll
            for (int dd = 0; dd < 16; dd++)
                part[i][dd] = 0.0f;

        #pragma unroll
        for (int j = 0; j < 16; j++) {
            const int c = cs * 16 + j;
            #pragma unroll
            for (int q = 0; q < 4; q++) {
                const int d4s = ((ch * 4 + q) ^ cs) & 15;
                float4 v4 = *(float4*)&vs[c * 64 + d4s * 4];
                #pragma unroll
                for (int i = 0; i < 4; i++) {
                    part[i][q * 4 + 0] = fmaf(acc[i][j], v4.x, part[i][q * 4 + 0]);
                    part[i][q * 4 + 1] = fmaf(acc[i][j], v4.y, part[i][q * 4 + 1]);
                    part[i][q * 4 + 2] = fmaf(acc[i][j], v4.z, part[i][q * 4 + 2]);
                    part[i][q * 4 + 3] = fmaf(acc[i][j], v4.w, part[i][q * 4 + 3]);
                }
            }
        }
        // butterfly-reduce across the 16 cs lanes
        #pragma unroll
        for (int o = 1; o < 16; o <<= 1)
            #pragma unroll
            for (int i = 0; i < 4; i++)
                #pragma unroll
                for (int dd = 0; dd < 16; dd++)
                    part[i][dd] += __shfl_xor_sync(0xffffffffu, part[i][dd], o, 16);

        // lane cs writes d = ch*16 + cs for each of its 4 rows
        #pragma unroll
        for (int i = 0; i < 4; i++)
            out[((b * 4096 + s_base + i) * 16 + head) * 64 + ch * 16 + cs] = part[i][cs];
    }
}

// ---------------------------------------------------------------------------
extern "C" void kernel_launch(void* const* d_in, const int* in_sizes, int n_in,
                              void* d_out, int out_size)
{
    const float* X    = (const float*)d_in[0];
    // d_in[1] = attention_mask (unused by reference)
    const int*   perm = (const int*)d_in[2];
    const float* Wq   = (const float*)d_in[3];
    const float* Bq   = (const float*)d_in[4];
    const float* Wk   = (const float*)d_in[5];
    const float* Bk   = (const float*)d_in[6];
    const float* Wv   = (const float*)d_in[7];
    const float* Bv   = (const float*)d_in[8];
    float* out        = (float*)d_out;

    (void)in_sizes; (void)n_in; (void)out_size;

    // Opt-in to 144 KB dynamic smem for the attention kernel (host-side
    // attribute set; capture-safe, idempotent).
    const int smem = (64 * 64 + 256 * 64 + 256 * 64) * (int)sizeof(float); // 144 KB
    cudaFuncSetAttribute(attn_kernel, cudaFuncAttributeMaxDynamicSharedMemorySize, smem);

    // QKV projections
    dim3 gg(8, 64, 3);   // N tiles, M tiles, {q,k,v}
    qkv_gemm<<<gg, 256>>>(X, Wq, Bq, Wk, Bk, Wv, Bv);

    // Attention
    dim3 ga(4, 256, 2);  // q-tiles, groups, batch
    attn_kernel<<<ga, 256, smem>>>(perm, out);
}

// round 5
// speedup vs baseline: 1.5516x; 1.5516x over previous
#include <cuda_runtime.h>
#include <cuda_bf16.h>
#include <math.h>
#include <stdint.h>

// ---------------------------------------------------------------------------
// Problem constants
// ---------------------------------------------------------------------------
#define SEQ     4096
#define HIDDEN  1024
#define BATCH   2
#define MROWS   (BATCH * SEQ)   // 8192

// Scratch: Q/K/V outputs in [B,S,nh,d] = [8192][1024] fp32
__device__ float g_Q[MROWS * HIDDEN];
__device__ float g_K[MROWS * HIDDEN];
__device__ float g_V[MROWS * HIDDEN];
// bf16 split operands
__device__ __nv_bfloat16 g_Xhi[MROWS * HIDDEN];
__device__ __nv_bfloat16 g_Xlo[MROWS * HIDDEN];
// W transposed to [proj*1024 + n][k] (K-major, i.e. col-major B for mma.sync)
__device__ __nv_bfloat16 g_Whi[3 * HIDDEN * HIDDEN];
__device__ __nv_bfloat16 g_Wlo[3 * HIDDEN * HIDDEN];

// ---------------------------------------------------------------------------
// PTX helpers (all plain-sm_100-legal: cp.async, ldmatrix, mma.sync)
// ---------------------------------------------------------------------------
__device__ __forceinline__ uint32_t smem_u32(const void* p) {
    uint32_t a;
    asm("{ .reg .u64 t; cvta.to.shared.u64 t, %1; cvt.u32.u64 %0, t; }" : "=r"(a) : "l"(p));
    return a;
}
#define CP_ASYNC16(dst, src) \
    asm volatile("cp.async.cg.shared.global [%0], [%1], 16;" :: "r"(dst), "l"(src) : "memory")
#define CP_COMMIT() asm volatile("cp.async.commit_group;" ::: "memory")
#define CP_WAIT1()  asm volatile("cp.async.wait_group 1;" ::: "memory")
#define CP_WAIT0()  asm volatile("cp.async.wait_group 0;" ::: "memory")

__device__ __forceinline__ void ldsm_x4(uint32_t* r, uint32_t addr) {
    asm volatile("ldmatrix.sync.aligned.m8n8.x4.shared.b16 {%0,%1,%2,%3}, [%4];"
                 : "=r"(r[0]), "=r"(r[1]), "=r"(r[2]), "=r"(r[3]) : "r"(addr));
}
__device__ __forceinline__ void mma_bf16(float* c, const uint32_t* a, const uint32_t* b) {
    asm volatile("mma.sync.aligned.m16n8k16.row.col.f32.bf16.bf16.f32 "
                 "{%0,%1,%2,%3}, {%4,%5,%6,%7}, {%8,%9}, {%0,%1,%2,%3};"
                 : "+f"(c[0]), "+f"(c[1]), "+f"(c[2]), "+f"(c[3])
                 : "r"(a[0]), "r"(a[1]), "r"(a[2]), "r"(a[3]), "r"(b[0]), "r"(b[1]));
}

// ---------------------------------------------------------------------------
// fp32 -> bf16 hi/lo split of X (elementwise, vectorized)
// ---------------------------------------------------------------------------
__global__ __launch_bounds__(256) void cvt_x(const float* __restrict__ X) {
    int i = blockIdx.x * 256 + threadIdx.x;           // float4 index
    float4 v = ((const float4*)X)[i];
    float f[4] = {v.x, v.y, v.z, v.w};
    __nv_bfloat16 h[4], l[4];
    #pragma unroll
    for (int j = 0; j < 4; j++) {
        h[j] = __float2bfloat16(f[j]);
        l[j] = __float2bfloat16(f[j] - __bfloat162float(h[j]));
    }
    ((__nv_bfloat162*)g_Xhi)[2 * i]     = __halves2bfloat162(h[0], h[1]);
    ((__nv_bfloat162*)g_Xhi)[2 * i + 1] = __halves2bfloat162(h[2], h[3]);
    ((__nv_bfloat162*)g_Xlo)[2 * i]     = __halves2bfloat162(l[0], l[1]);
    ((__nv_bfloat162*)g_Xlo)[2 * i + 1] = __halves2bfloat162(l[2], l[3]);
}

// ---------------------------------------------------------------------------
// W [k][n] fp32  ->  Whi/Wlo [proj*1024+n][k] bf16 (transpose + split)
// ---------------------------------------------------------------------------
__global__ void cvt_w(const float* __restrict__ Wq,
                      const float* __restrict__ Wk,
                      const float* __restrict__ Wv) {
    __shared__ float s[32][33];
    const int proj = blockIdx.z;
    const float* W = proj == 0 ? Wq : (proj == 1 ? Wk : Wv);
    const int k0 = blockIdx.x * 32, n0 = blockIdx.y * 32;
    const int tx = threadIdx.x, ty = threadIdx.y;
    #pragma unroll
    for (int j = 0; j < 32; j += 8)
        s[ty + j][tx] = W[(k0 + ty + j) * 1024 + n0 + tx];
    __syncthreads();
    #pragma unroll
    for (int j = 0; j < 32; j += 8) {
        float v = s[tx][ty + j];                      // W[k0+tx][n0+ty+j]
        int n = n0 + ty + j, k = k0 + tx;
        __nv_bfloat16 hi = __float2bfloat16(v);
        __nv_bfloat16 lo = __float2bfloat16(v - __bfloat162float(hi));
        size_t o = ((size_t)proj * 1024 + n) * 1024 + k;
        g_Whi[o] = hi;
        g_Wlo[o] = lo;
    }
}

// ---------------------------------------------------------------------------
// Projection GEMM on tensor cores via mma.sync bf16, split-precision (3 terms).
// CTA tile 128(M)x128(N), 256 threads = 8 warps (4m x 2n), warp tile 32x64.
// K chunks of 32 halves, cp.async double-buffered.
// smem row = 32 halves at pitch 80B (conflict-free ldmatrix: start banks
// (20r+4c) mod 32 distinct over any 8 consecutive rows).
// ---------------------------------------------------------------------------
#define PITCHB     80
#define MAT_BYTES  (128 * PITCHB)      // 10240
#define A_HI       0
#define A_LO       (1 * MAT_BYTES)
#define B_HI       (2 * MAT_BYTES)
#define B_LO       (3 * MAT_BYTES)
#define BUF_BYTES  (4 * MAT_BYTES)     // 40960
#define GEMM_SMEM  (2 * BUF_BYTES)     // 81920

__global__ __launch_bounds__(256) void qkv_gemm_mma(
    const float* __restrict__ Bq, const float* __restrict__ Bk,
    const float* __restrict__ Bv) {
    extern __shared__ __align__(128) char smem[];
    const uint32_t sb = smem_u32(smem);
    const int t = threadIdx.x, lane = t & 31, wid = t >> 5;
    const int warp_m = wid >> 1, warp_n = wid & 1;
    const int m0 = blockIdx.y * 128;
    const int n0g = blockIdx.x * 128;              // 0..3071
    const int proj = n0g >> 10;
    const int col0 = n0g & 1023;
    const float* Bias = proj == 0 ? Bq : (proj == 1 ? Bk : Bv);
    float* Out = proj == 0 ? g_Q : (proj == 1 ? g_K : g_V);

    __shared__ float sbias[128];
    if (t < 128) sbias[t] = Bias[col0 + t];

    // per-thread gmem rows (one 64B row-chunk per matrix per chunk)
    const int lrow = t >> 1;                        // 0..127
    const __nv_bfloat16* gAh = g_Xhi + (size_t)(m0 + lrow) * 1024;
    const __nv_bfloat16* gAl = g_Xlo + (size_t)(m0 + lrow) * 1024;
    const __nv_bfloat16* gBh = g_Whi + (size_t)(n0g + lrow) * 1024;
    const __nv_bfloat16* gBl = g_Wlo + (size_t)(n0g + lrow) * 1024;

    auto load_chunk = [&](int buf, int kc) {
        uint32_t base = sb + buf * BUF_BYTES + lrow * PITCHB;
        #pragma unroll
        for (int c2 = 0; c2 < 2; c2++) {
            int c = (t & 1) * 2 + c2;               // 16B chunk within 64B row
            uint32_t sw = c * 16;
            int go = kc + c * 8;
            CP_ASYNC16(base + A_HI + sw, gAh + go);
            CP_ASYNC16(base + A_LO + sw, gAl + go);
            CP_ASYNC16(base + B_HI + sw, gBh + go);
            CP_ASYNC16(base + B_LO + sw, gBl + go);
        }
    };

    float C[2][8][4];
    #pragma unroll
    for (int mt = 0; mt < 2; mt++)
        #pragma unroll
        for (int nt = 0; nt < 8; nt++)
            #pragma unroll
            for (int j = 0; j < 4; j++) C[mt][nt][j] = 0.0f;

    load_chunk(0, 0);
    CP_COMMIT();

    // ldmatrix base offsets (within a buffer)
    const uint32_t a_row = (uint32_t)(warp_m * 32 + (lane & 15)) * PITCHB
                         + (uint32_t)(lane >> 4) * 16;
    const uint32_t b_row = (uint32_t)(warp_n * 64 + ((lane >> 4) << 3) + (lane & 7)) * PITCHB
                         + (uint32_t)((lane >> 3) & 1) * 16;

    for (int ch = 0; ch < 32; ch++) {
        const int buf = ch & 1;
        if (ch + 1 < 32) {
            load_chunk(buf ^ 1, (ch + 1) * 32);
            CP_COMMIT();
            CP_WAIT1();
        } else {
            CP_WAIT0();
        }
        __syncthreads();

        const uint32_t base = sb + buf * BUF_BYTES;
        #pragma unroll
        for (int ks = 0; ks < 2; ks++) {
            uint32_t a_hi[2][4], a_lo[2][4];
            #pragma unroll
            for (int mt = 0; mt < 2; mt++) {
                uint32_t ra = base + a_row + mt * (16 * PITCHB) + ks * 32;
                ldsm_x4(a_hi[mt], ra + A_HI);
                ldsm_x4(a_lo[mt], ra + A_LO);
            }
            uint32_t b_hi[8][2], b_lo[8][2];
            #pragma unroll
            for (int p = 0; p < 4; p++) {           // pairs of n-tiles
                uint32_t rb = base + b_row + p * (16 * PITCHB) + ks * 32;
                uint32_t rr[4];
                ldsm_x4(rr, rb + B_HI);
                b_hi[p * 2][0] = rr[0]; b_hi[p * 2][1] = rr[1];
                b_hi[p * 2 + 1][0] = rr[2]; b_hi[p * 2 + 1][1] = rr[3];
                ldsm_x4(rr, rb + B_LO);
                b_lo[p * 2][0] = rr[0]; b_lo[p * 2][1] = rr[1];
                b_lo[p * 2 + 1][0] = rr[2]; b_lo[p * 2 + 1][1] = rr[3];
            }
            #pragma unroll
            for (int mt = 0; mt < 2; mt++)
                #pragma unroll
                for (int nt = 0; nt < 8; nt++) {
                    mma_bf16(C[mt][nt], a_hi[mt], b_hi[nt]);
                    mma_bf16(C[mt][nt], a_hi[mt], b_lo[nt]);
                    mma_bf16(C[mt][nt], a_lo[mt], b_hi[nt]);
                }
        }
        __syncthreads();   // all reads of buf done before it is refilled
    }

    // epilogue: C fragment rows (lane>>2, +8), cols (lane&3)*2,+1
    #pragma unroll
    for (int mt = 0; mt < 2; mt++) {
        const int row0 = m0 + warp_m * 32 + mt * 16 + (lane >> 2);
        #pragma unroll
        for (int nt = 0; nt < 8; nt++) {
            const int col = warp_n * 64 + nt * 8 + (lane & 3) * 2;
            float2 v0 = make_float2(C[mt][nt][0] + sbias[col],
                                    C[mt][nt][1] + sbias[col + 1]);
            float2 v1 = make_float2(C[mt][nt][2] + sbias[col],
                                    C[mt][nt][3] + sbias[col + 1]);
            *(float2*)&Out[(size_t)row0 * 1024 + col0 + col] = v0;
            *(float2*)&Out[(size_t)(row0 + 8) * 1024 + col0 + col] = v1;
        }
    }
}

// ---------------------------------------------------------------------------
// Block-local attention, permuted K/V groups.
// CTA = (64-row q tile, group, batch). smem: qs 16K | ks 64K | vs 64K.
// Logits via fp32 FMA; AV via P staged in smem (overlays qs+ks), no shuffles.
// ---------------------------------------------------------------------------
#define PPITCH 268   // floats

__global__ __launch_bounds__(256) void attn_kernel(
    const int* __restrict__ perm,
    float* __restrict__ out) {
    extern __shared__ float sm[];
    float* qs = sm;                  // 64*64
    float* ks = sm + 64 * 64;        // 256*64 swizzled
    float* vs = ks + 256 * 64;       // 256*64 swizzled
    float* P  = sm;                  // 64 x PPITCH, overlays qs+ks after logits

    const int qt = blockIdx.x;       // 0..3
    const int g  = blockIdx.y;       // 0..255
    const int b  = blockIdx.z;
    const int blk = g >> 4, head = g & 15;
    const int src = perm[g];
    const int sblk = src >> 4, shead = src & 15;

    const int t  = threadIdx.x;
    const int rs = t >> 4;           // 0..15
    const int cs = t & 15;           // 0..15
    const int r0 = rs * 4;

    // load q tile
    {
        const int base_s = blk * 256 + qt * 64;
        for (int i = t; i < 64 * 16; i += 256) {
            int r = i >> 4, f4 = i & 15;
            float4 v = *(const float4*)&g_Q[((b * 4096 + base_s + r) * 16 + head) * 64 + f4 * 4];
            *(float4*)&qs[r * 64 + f4 * 4] = v;
        }
    }
    // load K/V (permuted source), XOR swizzle at 16B granularity
    {
        const int base_s = sblk * 256;
        for (int i = t; i < 256 * 16; i += 256) {
            int c = i >> 4, f4 = i & 15;
            int f4s = (f4 ^ (c >> 4)) & 15;
            int gidx = ((b * 4096 + base_s + c) * 16 + shead) * 64 + f4 * 4;
            float4 kv = *(const float4*)&g_K[gidx];
            *(float4*)&ks[c * 64 + f4s * 4] = kv;
            float4 vv = *(const float4*)&g_V[gidx];
            *(float4*)&vs[c * 64 + f4s * 4] = vv;
        }
    }
    __syncthreads();

    // logits: acc[i][j] = q[r0+i] . k[cs*16+j]
    float acc[4][16];
    #pragma unroll
    for (int i = 0; i < 4; i++)
        #pragma unroll
        for (int j = 0; j < 16; j++) acc[i][j] = 0.0f;

    for (int d = 0; d < 64; d += 4) {
        float4 q4[4];
        #pragma unroll
        for (int i = 0; i < 4; i++) q4[i] = *(float4*)&qs[(r0 + i) * 64 + d];
        #pragma unroll
        for (int j = 0; j < 16; j++) {
            const int c = cs * 16 + j;
            const int d4s = ((d >> 2) ^ (c >> 4)) & 15;
            float4 kv = *(float4*)&ks[c * 64 + d4s * 4];
            #pragma unroll
            for (int i = 0; i < 4; i++) {
                acc[i][j] = fmaf(q4[i].x, kv.x, acc[i][j]);
                acc[i][j] = fmaf(q4[i].y, kv.y, acc[i][j]);
                acc[i][j] = fmaf(q4[i].z, kv.z, acc[i][j]);
                acc[i][j] = fmaf(q4[i].w, kv.w, acc[i][j]);
            }
        }
    }
    __syncthreads();   // all ks/qs reads done before P overlays them

    // softmax (scale 1/8), 16-lane shuffle reductions
    const float scale = 0.125f;
    #pragma unroll
    for (int i = 0; i < 4; i++) {
        float m = acc[i][0];
        #pragma unroll
        for (int j = 1; j < 16; j++) m = fmaxf(m, acc[i][j]);
        #pragma unroll
        for (int o = 8; o >= 1; o >>= 1)
            m = fmaxf(m, __shfl_xor_sync(0xffffffffu, m, o, 16));
        float s = 0.0f;
        #pragma unroll
        for (int j = 0; j < 16; j++) { acc[i][j] = __expf(scale * (acc[i][j] - m)); s += acc[i][j]; }
        #pragma unroll
        for (int o = 8; o >= 1; o >>= 1)
            s += __shfl_xor_sync(0xffffffffu, s, o, 16);
        float is = 1.0f / s;
        #pragma unroll
        for (int j = 0; j < 16; j++) acc[i][j] *= is;
    }

    // stage P[64][256] in smem
    #pragma unroll
    for (int i = 0; i < 4; i++)
        #pragma unroll
        for (int jq = 0; jq < 4; jq++) {
            float4 v = make_float4(acc[i][jq * 4], acc[i][jq * 4 + 1],
                                   acc[i][jq * 4 + 2], acc[i][jq * 4 + 3]);
            *(float4*)&P[(r0 + i) * PPITCH + cs * 16 + jq * 4] = v;
        }
    __syncthreads();

    // AV: thread owns rows r0..r0+3, cols cs*4..cs*4+3; full k range, no shuffles
    float av[4][4];
    #pragma unroll
    for (int i = 0; i < 4; i++)
        #pragma unroll
        for (int d = 0; d < 4; d++) av[i][d] = 0.0f;

    for (int k0 = 0; k0 < 256; k0 += 4) {
        float pr[4][4];
        #pragma unroll
        for (int i = 0; i < 4; i++) {
            float4 p4 = *(float4*)&P[(r0 + i) * PPITCH + k0];
            pr[i][0] = p4.x; pr[i][1] = p4.y; pr[i][2] = p4.z; pr[i][3] = p4.w;
        }
        #pragma unroll
        for (int kk = 0; kk < 4; kk++) {
            const int c = k0 + kk;
            float4 v4 = *(float4*)&vs[c * 64 + ((cs ^ (c >> 4)) & 15) * 4];
            #pragma unroll
            for (int i = 0; i < 4; i++) {
                av[i][0] = fmaf(pr[i][kk], v4.x, av[i][0]);
                av[i][1] = fmaf(pr[i][kk], v4.y, av[i][1]);
                av[i][2] = fmaf(pr[i][kk], v4.z, av[i][2]);
                av[i][3] = fmaf(pr[i][kk], v4.w, av[i][3]);
            }
        }
    }

    const int s_base = blk * 256 + qt * 64 + r0;
    #pragma unroll
    for (int i = 0; i < 4; i++) {
        float4 v = make_float4(av[i][0], av[i][1], av[i][2], av[i][3]);
        *(float4*)&out[((b * 4096 + s_base + i) * 16 + head) * 64 + cs * 4] = v;
    }
}

// ---------------------------------------------------------------------------
extern "C" void kernel_launch(void* const* d_in, const int* in_sizes, int n_in,
                              void* d_out, int out_size) {
    const float* X    = (const float*)d_in[0];
    const int*   perm = (const int*)d_in[2];
    const float* Wq   = (const float*)d_in[3];
    const float* Bq   = (const float*)d_in[4];
    const float* Wk   = (const float*)d_in[5];
    const float* Bk   = (const float*)d_in[6];
    const float* Wv   = (const float*)d_in[7];
    const float* Bv   = (const float*)d_in[8];
    float* out        = (float*)d_out;
    (void)in_sizes; (void)n_in; (void)out_size;

    cudaFuncSetAttribute(qkv_gemm_mma, cudaFuncAttributeMaxDynamicSharedMemorySize, GEMM_SMEM);
    const int asmem = (64 * 64 + 256 * 64 + 256 * 64) * (int)sizeof(float); // 144 KB
    cudaFuncSetAttribute(attn_kernel, cudaFuncAttributeMaxDynamicSharedMemorySize, asmem);

    // split X and W into bf16 hi/lo
    cvt_x<<<MROWS * HIDDEN / 4 / 256, 256>>>(X);
    cvt_w<<<dim3(32, 32, 3), dim3(32, 8)>>>(Wq, Wk, Wv);

    // tensor-core projection GEMM: 24 n-tiles (3 projections x 8), 64 m-tiles
    qkv_gemm_mma<<<dim3(24, 64), 256, GEMM_SMEM>>>(Bq, Bk, Bv);

    // attention
    attn_kernel<<<dim3(4, 256, 2), 256, asmem>>>(perm, out);
}

// round 6
// speedup vs baseline: 1.5600x; 1.0054x over previous
#include <cuda_runtime.h>
#include <cuda_bf16.h>
#include <math.h>
#include <stdint.h>

// ---------------------------------------------------------------------------
// Problem constants
// ---------------------------------------------------------------------------
#define SEQ     4096
#define HIDDEN  1024
#define BATCH   2
#define MROWS   (BATCH * SEQ)   // 8192

// Scratch: Q/K/V outputs in [B,S,nh,d] = [8192][1024] fp32
__device__ float g_Q[MROWS * HIDDEN];
__device__ float g_K[MROWS * HIDDEN];
__device__ float g_V[MROWS * HIDDEN];
// bf16 split operands
__device__ __nv_bfloat16 g_Xhi[MROWS * HIDDEN];
__device__ __nv_bfloat16 g_Xlo[MROWS * HIDDEN];
// W transposed to [proj*1024 + n][k] (K-major, i.e. col-major B for mma.sync)
__device__ __nv_bfloat16 g_Whi[3 * HIDDEN * HIDDEN];
__device__ __nv_bfloat16 g_Wlo[3 * HIDDEN * HIDDEN];

// ---------------------------------------------------------------------------
// PTX helpers (all plain-sm_100-legal: cp.async, ldmatrix, mma.sync)
// ---------------------------------------------------------------------------
__device__ __forceinline__ uint32_t smem_u32(const void* p) {
    uint32_t a;
    asm("{ .reg .u64 t; cvta.to.shared.u64 t, %1; cvt.u32.u64 %0, t; }" : "=r"(a) : "l"(p));
    return a;
}
#define CP_ASYNC16(dst, src) \
    asm volatile("cp.async.cg.shared.global [%0], [%1], 16;" :: "r"(dst), "l"(src) : "memory")
#define CP_COMMIT() asm volatile("cp.async.commit_group;" ::: "memory")
#define CP_WAIT2()  asm volatile("cp.async.wait_group 2;" ::: "memory")
#define CP_WAIT1()  asm volatile("cp.async.wait_group 1;" ::: "memory")
#define CP_WAIT0()  asm volatile("cp.async.wait_group 0;" ::: "memory")

__device__ __forceinline__ void ldsm_x4(uint32_t* r, uint32_t addr) {
    asm volatile("ldmatrix.sync.aligned.m8n8.x4.shared.b16 {%0,%1,%2,%3}, [%4];"
                 : "=r"(r[0]), "=r"(r[1]), "=r"(r[2]), "=r"(r[3]) : "r"(addr));
}
__device__ __forceinline__ void mma_bf16(float* c, const uint32_t* a, const uint32_t* b) {
    asm volatile("mma.sync.aligned.m16n8k16.row.col.f32.bf16.bf16.f32 "
                 "{%0,%1,%2,%3}, {%4,%5,%6,%7}, {%8,%9}, {%0,%1,%2,%3};"
                 : "+f"(c[0]), "+f"(c[1]), "+f"(c[2]), "+f"(c[3])
                 : "r"(a[0]), "r"(a[1]), "r"(a[2]), "r"(a[3]), "r"(b[0]), "r"(b[1]));
}

// Fast exp on the FMA pipe (no MUFU). |rel err| < 3e-6 for t in [-80, 0].
__device__ __forceinline__ float fast_exp(float t) {
    float y = t * 1.442695041f;                 // log2(e)
    float z = y + 12582912.0f;                  // 1.5 * 2^23 round-to-nearest
    float n = z - 12582912.0f;
    float f = y - n;                            // f in [-0.5, 0.5]
    float p =            1.33336e-3f;
    p = fmaf(p, f,       9.61815e-3f);
    p = fmaf(p, f,       5.55042e-2f);
    p = fmaf(p, f,       2.40226e-1f);
    p = fmaf(p, f,       6.93147e-1f);
    p = fmaf(p, f,       1.0f);
    int e = __float2int_rn(n);
    float s = __int_as_float((e + 127) << 23);  // 2^n (n bounded, no overflow)
    return s * p;
}

// ---------------------------------------------------------------------------
// fp32 -> bf16 hi/lo split of X (elementwise, vectorized)
// ---------------------------------------------------------------------------
__global__ __launch_bounds__(256) void cvt_x(const float* __restrict__ X) {
    int i = blockIdx.x * 256 + threadIdx.x;           // float4 index
    float4 v = ((const float4*)X)[i];
    float f[4] = {v.x, v.y, v.z, v.w};
    __nv_bfloat16 h[4], l[4];
    #pragma unroll
    for (int j = 0; j < 4; j++) {
        h[j] = __float2bfloat16(f[j]);
        l[j] = __float2bfloat16(f[j] - __bfloat162float(h[j]));
    }
    ((__nv_bfloat162*)g_Xhi)[2 * i]     = __halves2bfloat162(h[0], h[1]);
    ((__nv_bfloat162*)g_Xhi)[2 * i + 1] = __halves2bfloat162(h[2], h[3]);
    ((__nv_bfloat162*)g_Xlo)[2 * i]     = __halves2bfloat162(l[0], l[1]);
    ((__nv_bfloat162*)g_Xlo)[2 * i + 1] = __halves2bfloat162(l[2], l[3]);
}

// ---------------------------------------------------------------------------
// W [k][n] fp32  ->  Whi/Wlo [proj*1024+n][k] bf16 (transpose + split)
// ---------------------------------------------------------------------------
__global__ void cvt_w(const float* __restrict__ Wq,
                      const float* __restrict__ Wk,
                      const float* __restrict__ Wv) {
    __shared__ float s[32][33];
    const int proj = blockIdx.z;
    const float* W = proj == 0 ? Wq : (proj == 1 ? Wk : Wv);
    const int k0 = blockIdx.x * 32, n0 = blockIdx.y * 32;
    const int tx = threadIdx.x, ty = threadIdx.y;
    #pragma unroll
    for (int j = 0; j < 32; j += 8)
        s[ty + j][tx] = W[(k0 + ty + j) * 1024 + n0 + tx];
    __syncthreads();
    #pragma unroll
    for (int j = 0; j < 32; j += 8) {
        float v = s[tx][ty + j];                      // W[k0+tx][n0+ty+j]
        int n = n0 + ty + j, k = k0 + tx;
        __nv_bfloat16 hi = __float2bfloat16(v);
        __nv_bfloat16 lo = __float2bfloat16(v - __bfloat162float(hi));
        size_t o = ((size_t)proj * 1024 + n) * 1024 + k;
        g_Whi[o] = hi;
        g_Wlo[o] = lo;
    }
}

// ---------------------------------------------------------------------------
// Projection GEMM on tensor cores via mma.sync bf16, split-precision (3 terms).
// CTA tile 128(M)x128(N), 256 threads = 8 warps (4m x 2n), warp tile 32x64.
// K chunks of 32 halves, cp.async 4-stage pipeline (2 chunks in flight).
// smem row = 32 halves at pitch 80B (conflict-free ldmatrix).
// ---------------------------------------------------------------------------
#define PITCHB     80
#define MAT_BYTES  (128 * PITCHB)      // 10240
#define A_HI       0
#define A_LO       (1 * MAT_BYTES)
#define B_HI       (2 * MAT_BYTES)
#define B_LO       (3 * MAT_BYTES)
#define BUF_BYTES  (4 * MAT_BYTES)     // 40960
#define NSTAGE     4
#define GEMM_SMEM  (NSTAGE * BUF_BYTES)   // 163840

__global__ __launch_bounds__(256) void qkv_gemm_mma(
    const float* __restrict__ Bq, const float* __restrict__ Bk,
    const float* __restrict__ Bv) {
    extern __shared__ __align__(128) char smem[];
    const uint32_t sb = smem_u32(smem);
    const int t = threadIdx.x, lane = t & 31, wid = t >> 5;
    const int warp_m = wid >> 1, warp_n = wid & 1;
    const int m0 = blockIdx.y * 128;
    const int n0g = blockIdx.x * 128;              // 0..3071
    const int proj = n0g >> 10;
    const int col0 = n0g & 1023;
    const float* Bias = proj == 0 ? Bq : (proj == 1 ? Bk : Bv);
    float* Out = proj == 0 ? g_Q : (proj == 1 ? g_K : g_V);

    __shared__ float sbias[128];
    if (t < 128) sbias[t] = Bias[col0 + t];

    // per-thread gmem rows (one 64B row-chunk per matrix per chunk)
    const int lrow = t >> 1;                        // 0..127
    const __nv_bfloat16* gAh = g_Xhi + (size_t)(m0 + lrow) * 1024;
    const __nv_bfloat16* gAl = g_Xlo + (size_t)(m0 + lrow) * 1024;
    const __nv_bfloat16* gBh = g_Whi + (size_t)(n0g + lrow) * 1024;
    const __nv_bfloat16* gBl = g_Wlo + (size_t)(n0g + lrow) * 1024;

    auto load_chunk = [&](int slot, int kc) {
        uint32_t base = sb + slot * BUF_BYTES + lrow * PITCHB;
        #pragma unroll
        for (int c2 = 0; c2 < 2; c2++) {
            int c = (t & 1) * 2 + c2;               // 16B chunk within 64B row
            uint32_t sw = c * 16;
            int go = kc + c * 8;
            CP_ASYNC16(base + A_HI + sw, gAh + go);
            CP_ASYNC16(base + A_LO + sw, gAl + go);
            CP_ASYNC16(base + B_HI + sw, gBh + go);
            CP_ASYNC16(base + B_LO + sw, gBl + go);
        }
    };

    float C[2][8][4];
    #pragma unroll
    for (int mt = 0; mt < 2; mt++)
        #pragma unroll
        for (int nt = 0; nt < 8; nt++)
            #pragma unroll
            for (int j = 0; j < 4; j++) C[mt][nt][j] = 0.0f;

    // prologue: 3 chunks in flight
    load_chunk(0, 0);  CP_COMMIT();
    load_chunk(1, 32); CP_COMMIT();
    load_chunk(2, 64); CP_COMMIT();

    // ldmatrix base offsets (within a buffer)
    const uint32_t a_row = (uint32_t)(warp_m * 32 + (lane & 15)) * PITCHB
                         + (uint32_t)(lane >> 4) * 16;
    const uint32_t b_row = (uint32_t)(warp_n * 64 + ((lane >> 4) << 3) + (lane & 7)) * PITCHB
                         + (uint32_t)((lane >> 3) & 1) * 16;

    for (int ch = 0; ch < 32; ch++) {
        // ensure chunk ch resident (tail: fewer groups outstanding)
        if (ch <= 29)      CP_WAIT2();
        else if (ch == 30) CP_WAIT1();
        else               CP_WAIT0();
        __syncthreads();   // data visible to all; slot (ch+3)%4 reads (chunk ch-1) drained

        if (ch + 3 < 32) {
            load_chunk((ch + 3) & (NSTAGE - 1), (ch + 3) * 32);
            CP_COMMIT();
        }

        const uint32_t base = sb + (ch & (NSTAGE - 1)) * BUF_BYTES;
        #pragma unroll
        for (int ks = 0; ks < 2; ks++) {
            uint32_t a_hi[2][4], a_lo[2][4];
            #pragma unroll
            for (int mt = 0; mt < 2; mt++) {
                uint32_t ra = base + a_row + mt * (16 * PITCHB) + ks * 32;
                ldsm_x4(a_hi[mt], ra + A_HI);
                ldsm_x4(a_lo[mt], ra + A_LO);
            }
            uint32_t b_hi[8][2], b_lo[8][2];
            #pragma unroll
            for (int p = 0; p < 4; p++) {           // pairs of n-tiles
                uint32_t rb = base + b_row + p * (16 * PITCHB) + ks * 32;
                uint32_t rr[4];
                ldsm_x4(rr, rb + B_HI);
                b_hi[p * 2][0] = rr[0]; b_hi[p * 2][1] = rr[1];
                b_hi[p * 2 + 1][0] = rr[2]; b_hi[p * 2 + 1][1] = rr[3];
                ldsm_x4(rr, rb + B_LO);
                b_lo[p * 2][0] = rr[0]; b_lo[p * 2][1] = rr[1];
                b_lo[p * 2 + 1][0] = rr[2]; b_lo[p * 2 + 1][1] = rr[3];
            }
            #pragma unroll
            for (int mt = 0; mt < 2; mt++)
                #pragma unroll
                for (int nt = 0; nt < 8; nt++) {
                    mma_bf16(C[mt][nt], a_hi[mt], b_hi[nt]);
                    mma_bf16(C[mt][nt], a_hi[mt], b_lo[nt]);
                    mma_bf16(C[mt][nt], a_lo[mt], b_hi[nt]);
                }
        }
    }

    // epilogue: C fragment rows (lane>>2, +8), cols (lane&3)*2,+1
    #pragma unroll
    for (int mt = 0; mt < 2; mt++) {
        const int row0 = m0 + warp_m * 32 + mt * 16 + (lane >> 2);
        #pragma unroll
        for (int nt = 0; nt < 8; nt++) {
            const int col = warp_n * 64 + nt * 8 + (lane & 3) * 2;
            float2 v0 = make_float2(C[mt][nt][0] + sbias[col],
                                    C[mt][nt][1] + sbias[col + 1]);
            float2 v1 = make_float2(C[mt][nt][2] + sbias[col],
                                    C[mt][nt][3] + sbias[col + 1]);
            *(float2*)&Out[(size_t)row0 * 1024 + col0 + col] = v0;
            *(float2*)&Out[(size_t)(row0 + 8) * 1024 + col0 + col] = v1;
        }
    }
}

// ---------------------------------------------------------------------------
// Block-local attention, permuted K/V groups.
// CTA = (64-row q tile, group, batch). smem: qs 16K | ks 64K | vs 64K.
// Logits via fp32 FMA; softmax exp on FMA pipe; AV via P staged in smem.
// ---------------------------------------------------------------------------
#define PPITCH 268   // floats

__global__ __launch_bounds__(256) void attn_kernel(
    const int* __restrict__ perm,
    float* __restrict__ out) {
    extern __shared__ float sm[];
    float* qs = sm;                  // 64*64
    float* ks = sm + 64 * 64;        // 256*64 swizzled
    float* vs = ks + 256 * 64;       // 256*64 swizzled
    float* P  = sm;                  // 64 x PPITCH, overlays qs+ks after logits

    const int qt = blockIdx.x;       // 0..3
    const int g  = blockIdx.y;       // 0..255
    const int b  = blockIdx.z;
    const int blk = g >> 4, head = g & 15;
    const int src = perm[g];
    const int sblk = src >> 4, shead = src & 15;

    const int t  = threadIdx.x;
    const int rs = t >> 4;           // 0..15
    const int cs = t & 15;           // 0..15
    const int r0 = rs * 4;

    // load q tile
    {
        const int base_s = blk * 256 + qt * 64;
        for (int i = t; i < 64 * 16; i += 256) {
            int r = i >> 4, f4 = i & 15;
            float4 v = *(const float4*)&g_Q[((b * 4096 + base_s + r) * 16 + head) * 64 + f4 * 4];
            *(float4*)&qs[r * 64 + f4 * 4] = v;
        }
    }
    // load K/V (permuted source), XOR swizzle at 16B granularity
    {
        const int base_s = sblk * 256;
        for (int i = t; i < 256 * 16; i += 256) {
            int c = i >> 4, f4 = i & 15;
            int f4s = (f4 ^ (c >> 4)) & 15;
            int gidx = ((b * 4096 + base_s + c) * 16 + shead) * 64 + f4 * 4;
            float4 kv = *(const float4*)&g_K[gidx];
            *(float4*)&ks[c * 64 + f4s * 4] = kv;
            float4 vv = *(const float4*)&g_V[gidx];
            *(float4*)&vs[c * 64 + f4s * 4] = vv;
        }
    }
    __syncthreads();

    // logits: acc[i][j] = q[r0+i] . k[cs*16+j]
    float acc[4][16];
    #pragma unroll
    for (int i = 0; i < 4; i++)
        #pragma unroll
        for (int j = 0; j < 16; j++) acc[i][j] = 0.0f;

    for (int d = 0; d < 64; d += 4) {
        float4 q4[4];
        #pragma unroll
        for (int i = 0; i < 4; i++) q4[i] = *(float4*)&qs[(r0 + i) * 64 + d];
        #pragma unroll
        for (int j = 0; j < 16; j++) {
            const int c = cs * 16 + j;
            const int d4s = ((d >> 2) ^ (c >> 4)) & 15;
            float4 kv = *(float4*)&ks[c * 64 + d4s * 4];
            #pragma unroll
            for (int i = 0; i < 4; i++) {
                acc[i][j] = fmaf(q4[i].x, kv.x, acc[i][j]);
                acc[i][j] = fmaf(q4[i].y, kv.y, acc[i][j]);
                acc[i][j] = fmaf(q4[i].z, kv.z, acc[i][j]);
                acc[i][j] = fmaf(q4[i].w, kv.w, acc[i][j]);
            }
        }
    }
    __syncthreads();   // all ks/qs reads done before P overlays them

    // softmax (scale 1/8), 16-lane shuffle reductions, FMA-pipe exp
    const float scale = 0.125f;
    #pragma unroll
    for (int i = 0; i < 4; i++) {
        float m = acc[i][0];
        #pragma unroll
        for (int j = 1; j < 16; j++) m = fmaxf(m, acc[i][j]);
        #pragma unroll
        for (int o = 8; o >= 1; o >>= 1)
            m = fmaxf(m, __shfl_xor_sync(0xffffffffu, m, o, 16));
        float s = 0.0f;
        #pragma unroll
        for (int j = 0; j < 16; j++) {
            acc[i][j] = fast_exp(scale * (acc[i][j] - m));
            s += acc[i][j];
        }
        #pragma unroll
        for (int o = 8; o >= 1; o >>= 1)
            s += __shfl_xor_sync(0xffffffffu, s, o, 16);
        float is = 1.0f / s;
        #pragma unroll
        for (int j = 0; j < 16; j++) acc[i][j] *= is;
    }

    // stage P[64][256] in smem
    #pragma unroll
    for (int i = 0; i < 4; i++)
        #pragma unroll
        for (int jq = 0; jq < 4; jq++) {
            float4 v = make_float4(acc[i][jq * 4], acc[i][jq * 4 + 1],
                                   acc[i][jq * 4 + 2], acc[i][jq * 4 + 3]);
            *(float4*)&P[(r0 + i) * PPITCH + cs * 16 + jq * 4] = v;
        }
    __syncthreads();

    // AV: thread owns rows r0..r0+3, cols cs*4..cs*4+3; full k range, no shuffles
    float av[4][4];
    #pragma unroll
    for (int i = 0; i < 4; i++)
        #pragma unroll
        for (int d = 0; d < 4; d++) av[i][d] = 0.0f;

    for (int k0 = 0; k0 < 256; k0 += 4) {
        float pr[4][4];
        #pragma unroll
        for (int i = 0; i < 4; i++) {
            float4 p4 = *(float4*)&P[(r0 + i) * PPITCH + k0];
            pr[i][0] = p4.x; pr[i][1] = p4.y; pr[i][2] = p4.z; pr[i][3] = p4.w;
        }
        #pragma unroll
        for (int kk = 0; kk < 4; kk++) {
            const int c = k0 + kk;
            float4 v4 = *(float4*)&vs[c * 64 + ((cs ^ (c >> 4)) & 15) * 4];
            #pragma unroll
            for (int i = 0; i < 4; i++) {
                av[i][0] = fmaf(pr[i][kk], v4.x, av[i][0]);
                av[i][1] = fmaf(pr[i][kk], v4.y, av[i][1]);
                av[i][2] = fmaf(pr[i][kk], v4.z, av[i][2]);
                av[i][3] = fmaf(pr[i][kk], v4.w, av[i][3]);
            }
        }
    }

    const int s_base = blk * 256 + qt * 64 + r0;
    #pragma unroll
    for (int i = 0; i < 4; i++) {
        float4 v = make_float4(av[i][0], av[i][1], av[i][2], av[i][3]);
        *(float4*)&out[((b * 4096 + s_base + i) * 16 + head) * 64 + cs * 4] = v;
    }
}

// ---------------------------------------------------------------------------
extern "C" void kernel_launch(void* const* d_in, const int* in_sizes, int n_in,
                              void* d_out, int out_size) {
    const float* X    = (const float*)d_in[0];
    const int*   perm = (const int*)d_in[2];
    const float* Wq   = (const float*)d_in[3];
    const float* Bq   = (const float*)d_in[4];
    const float* Wk   = (const float*)d_in[5];
    const float* Bk   = (const float*)d_in[6];
    const float* Wv   = (const float*)d_in[7];
    const float* Bv   = (const float*)d_in[8];
    float* out        = (float*)d_out;
    (void)in_sizes; (void)n_in; (void)out_size;

    cudaFuncSetAttribute(qkv_gemm_mma, cudaFuncAttributeMaxDynamicSharedMemorySize, GEMM_SMEM);
    const int asmem = (64 * 64 + 256 * 64 + 256 * 64) * (int)sizeof(float); // 144 KB
    cudaFuncSetAttribute(attn_kernel, cudaFuncAttributeMaxDynamicSharedMemorySize, asmem);

    // split X and W into bf16 hi/lo
    cvt_x<<<MROWS * HIDDEN / 4 / 256, 256>>>(X);
    cvt_w<<<dim3(32, 32, 3), dim3(32, 8)>>>(Wq, Wk, Wv);

    // tensor-core projection GEMM: 24 n-tiles (3 projections x 8), 64 m-tiles
    qkv_gemm_mma<<<dim3(24, 64), 256, GEMM_SMEM>>>(Bq, Bk, Bv);

    // attention
    attn_kernel<<<dim3(4, 256, 2), 256, asmem>>>(perm, out);
}

// round 7
// speedup vs baseline: 2.0633x; 1.3226x over previous
#include <cuda_runtime.h>
#include <cuda_bf16.h>
#include <math.h>
#include <stdint.h>

// ---------------------------------------------------------------------------
// Problem constants
// ---------------------------------------------------------------------------
#define SEQ     4096
#define HIDDEN  1024
#define BATCH   2
#define MROWS   (BATCH * SEQ)   // 8192
#define MH      (MROWS * HIDDEN)

// bf16 split operands for projection GEMM
__device__ __nv_bfloat16 g_Xhi[MH];
__device__ __nv_bfloat16 g_Xlo[MH];
__device__ __nv_bfloat16 g_Whi[3 * HIDDEN * HIDDEN];
__device__ __nv_bfloat16 g_Wlo[3 * HIDDEN * HIDDEN];
// Projection outputs as bf16 hi/lo: [proj][m 8192][col 1024] (col = head*64+d)
__device__ __nv_bfloat16 g_Ohi[3 * MH];
__device__ __nv_bfloat16 g_Olo[3 * MH];
// V transposed: [b 2][head 16][d 64][s 4096]
__device__ __nv_bfloat16 g_VThi[2 * 16 * 64 * 4096];
__device__ __nv_bfloat16 g_VTlo[2 * 16 * 64 * 4096];

// ---------------------------------------------------------------------------
// PTX helpers (plain-sm_100-legal: cp.async, ldmatrix, mma.sync)
// ---------------------------------------------------------------------------
__device__ __forceinline__ uint32_t smem_u32(const void* p) {
    uint32_t a;
    asm("{ .reg .u64 t; cvta.to.shared.u64 t, %1; cvt.u32.u64 %0, t; }" : "=r"(a) : "l"(p));
    return a;
}
#define CP_ASYNC16(dst, src) \
    asm volatile("cp.async.cg.shared.global [%0], [%1], 16;" :: "r"(dst), "l"(src) : "memory")
#define CP_COMMIT() asm volatile("cp.async.commit_group;" ::: "memory")
#define CP_WAIT2()  asm volatile("cp.async.wait_group 2;" ::: "memory")
#define CP_WAIT1()  asm volatile("cp.async.wait_group 1;" ::: "memory")
#define CP_WAIT0()  asm volatile("cp.async.wait_group 0;" ::: "memory")

__device__ __forceinline__ void ldsm_x4(uint32_t* r, uint32_t addr) {
    asm volatile("ldmatrix.sync.aligned.m8n8.x4.shared.b16 {%0,%1,%2,%3}, [%4];"
                 : "=r"(r[0]), "=r"(r[1]), "=r"(r[2]), "=r"(r[3]) : "r"(addr));
}
__device__ __forceinline__ void mma_bf16(float* c, const uint32_t* a, const uint32_t* b) {
    asm volatile("mma.sync.aligned.m16n8k16.row.col.f32.bf16.bf16.f32 "
                 "{%0,%1,%2,%3}, {%4,%5,%6,%7}, {%8,%9}, {%0,%1,%2,%3};"
                 : "+f"(c[0]), "+f"(c[1]), "+f"(c[2]), "+f"(c[3])
                 : "r"(a[0]), "r"(a[1]), "r"(a[2]), "r"(a[3]), "r"(b[0]), "r"(b[1]));
}
// Fast exp on the FMA pipe. |rel err| < 3e-6 for t in [-80, 0].
__device__ __forceinline__ float fast_exp(float t) {
    float y = t * 1.442695041f;
    float z = y + 12582912.0f;
    float n = z - 12582912.0f;
    float f = y - n;
    float p =            1.33336e-3f;
    p = fmaf(p, f,       9.61815e-3f);
    p = fmaf(p, f,       5.55042e-2f);
    p = fmaf(p, f,       2.40226e-1f);
    p = fmaf(p, f,       6.93147e-1f);
    p = fmaf(p, f,       1.0f);
    int e = __float2int_rn(n);
    float s = __int_as_float((e + 127) << 23);
    return s * p;
}
__device__ __forceinline__ uint32_t pack_bf16(float a, float b) {
    __nv_bfloat162 h = __floats2bfloat162_rn(a, b);   // .x = a (low), .y = b (high)
    return *(uint32_t*)&h;
}

// ---------------------------------------------------------------------------
// fp32 -> bf16 hi/lo split of X
// ---------------------------------------------------------------------------
__global__ __launch_bounds__(256) void cvt_x(const float* __restrict__ X) {
    int i = blockIdx.x * 256 + threadIdx.x;
    float4 v = ((const float4*)X)[i];
    float f[4] = {v.x, v.y, v.z, v.w};
    __nv_bfloat16 h[4], l[4];
    #pragma unroll
    for (int j = 0; j < 4; j++) {
        h[j] = __float2bfloat16(f[j]);
        l[j] = __float2bfloat16(f[j] - __bfloat162float(h[j]));
    }
    ((__nv_bfloat162*)g_Xhi)[2 * i]     = __halves2bfloat162(h[0], h[1]);
    ((__nv_bfloat162*)g_Xhi)[2 * i + 1] = __halves2bfloat162(h[2], h[3]);
    ((__nv_bfloat162*)g_Xlo)[2 * i]     = __halves2bfloat162(l[0], l[1]);
    ((__nv_bfloat162*)g_Xlo)[2 * i + 1] = __halves2bfloat162(l[2], l[3]);
}

// ---------------------------------------------------------------------------
// W [k][n] fp32 -> Whi/Wlo [proj*1024+n][k] bf16 (transpose + split)
// ---------------------------------------------------------------------------
__global__ void cvt_w(const float* __restrict__ Wq,
                      const float* __restrict__ Wk,
                      const float* __restrict__ Wv) {
    __shared__ float s[32][33];
    const int proj = blockIdx.z;
    const float* W = proj == 0 ? Wq : (proj == 1 ? Wk : Wv);
    const int k0 = blockIdx.x * 32, n0 = blockIdx.y * 32;
    const int tx = threadIdx.x, ty = threadIdx.y;
    #pragma unroll
    for (int j = 0; j < 32; j += 8)
        s[ty + j][tx] = W[(k0 + ty + j) * 1024 + n0 + tx];
    __syncthreads();
    #pragma unroll
    for (int j = 0; j < 32; j += 8) {
        float v = s[tx][ty + j];
        int n = n0 + ty + j, k = k0 + tx;
        __nv_bfloat16 hi = __float2bfloat16(v);
        __nv_bfloat16 lo = __float2bfloat16(v - __bfloat162float(hi));
        size_t o = ((size_t)proj * 1024 + n) * 1024 + k;
        g_Whi[o] = hi;
        g_Wlo[o] = lo;
    }
}

// ---------------------------------------------------------------------------
// Projection GEMM (mma.sync bf16, 3-term split). 128x128 CTA tile, 8 warps.
// Epilogue writes bf16 hi/lo pairs (Q,K,V all in g_Ohi/g_Olo).
// ---------------------------------------------------------------------------
#define PITCHB     80
#define MAT_BYTES  (128 * PITCHB)
#define A_HI       0
#define A_LO       (1 * MAT_BYTES)
#define B_HI       (2 * MAT_BYTES)
#define B_LO       (3 * MAT_BYTES)
#define BUF_BYTES  (4 * MAT_BYTES)
#define NSTAGE     4
#define GEMM_SMEM  (NSTAGE * BUF_BYTES)

__global__ __launch_bounds__(256) void qkv_gemm_mma(
    const float* __restrict__ Bq, const float* __restrict__ Bk,
    const float* __restrict__ Bv) {
    extern __shared__ __align__(128) char smem[];
    const uint32_t sb = smem_u32(smem);
    const int t = threadIdx.x, lane = t & 31, wid = t >> 5;
    const int warp_m = wid >> 1, warp_n = wid & 1;
    const int m0 = blockIdx.y * 128;
    const int n0g = blockIdx.x * 128;
    const int proj = n0g >> 10;
    const int col0 = n0g & 1023;
    const float* Bias = proj == 0 ? Bq : (proj == 1 ? Bk : Bv);
    __nv_bfloat16* OutHi = g_Ohi + (size_t)proj * MH;
    __nv_bfloat16* OutLo = g_Olo + (size_t)proj * MH;

    __shared__ float sbias[128];
    if (t < 128) sbias[t] = Bias[col0 + t];

    const int lrow = t >> 1;
    const __nv_bfloat16* gAh = g_Xhi + (size_t)(m0 + lrow) * 1024;
    const __nv_bfloat16* gAl = g_Xlo + (size_t)(m0 + lrow) * 1024;
    const __nv_bfloat16* gBh = g_Whi + (size_t)(n0g + lrow) * 1024;
    const __nv_bfloat16* gBl = g_Wlo + (size_t)(n0g + lrow) * 1024;

    auto load_chunk = [&](int slot, int kc) {
        uint32_t base = sb + slot * BUF_BYTES + lrow * PITCHB;
        #pragma unroll
        for (int c2 = 0; c2 < 2; c2++) {
            int c = (t & 1) * 2 + c2;
            uint32_t sw = c * 16;
            int go = kc + c * 8;
            CP_ASYNC16(base + A_HI + sw, gAh + go);
            CP_ASYNC16(base + A_LO + sw, gAl + go);
            CP_ASYNC16(base + B_HI + sw, gBh + go);
            CP_ASYNC16(base + B_LO + sw, gBl + go);
        }
    };

    float C[2][8][4];
    #pragma unroll
    for (int mt = 0; mt < 2; mt++)
        #pragma unroll
        for (int nt = 0; nt < 8; nt++)
            #pragma unroll
            for (int j = 0; j < 4; j++) C[mt][nt][j] = 0.0f;

    load_chunk(0, 0);  CP_COMMIT();
    load_chunk(1, 32); CP_COMMIT();
    load_chunk(2, 64); CP_COMMIT();

    const uint32_t a_row = (uint32_t)(warp_m * 32 + (lane & 15)) * PITCHB
                         + (uint32_t)(lane >> 4) * 16;
    const uint32_t b_row = (uint32_t)(warp_n * 64 + ((lane >> 4) << 3) + (lane & 7)) * PITCHB
                         + (uint32_t)((lane >> 3) & 1) * 16;

    for (int ch = 0; ch < 32; ch++) {
        if (ch <= 29)      CP_WAIT2();
        else if (ch == 30) CP_WAIT1();
        else               CP_WAIT0();
        __syncthreads();

        if (ch + 3 < 32) {
            load_chunk((ch + 3) & (NSTAGE - 1), (ch + 3) * 32);
            CP_COMMIT();
        }

        const uint32_t base = sb + (ch & (NSTAGE - 1)) * BUF_BYTES;
        #pragma unroll
        for (int ks = 0; ks < 2; ks++) {
            uint32_t a_hi[2][4], a_lo[2][4];
            #pragma unroll
            for (int mt = 0; mt < 2; mt++) {
                uint32_t ra = base + a_row + mt * (16 * PITCHB) + ks * 32;
                ldsm_x4(a_hi[mt], ra + A_HI);
                ldsm_x4(a_lo[mt], ra + A_LO);
            }
            uint32_t b_hi[8][2], b_lo[8][2];
            #pragma unroll
            for (int p = 0; p < 4; p++) {
                uint32_t rb = base + b_row + p * (16 * PITCHB) + ks * 32;
                uint32_t rr[4];
                ldsm_x4(rr, rb + B_HI);
                b_hi[p * 2][0] = rr[0]; b_hi[p * 2][1] = rr[1];
                b_hi[p * 2 + 1][0] = rr[2]; b_hi[p * 2 + 1][1] = rr[3];
                ldsm_x4(rr, rb + B_LO);
                b_lo[p * 2][0] = rr[0]; b_lo[p * 2][1] = rr[1];
                b_lo[p * 2 + 1][0] = rr[2]; b_lo[p * 2 + 1][1] = rr[3];
            }
            #pragma unroll
            for (int mt = 0; mt < 2; mt++)
                #pragma unroll
                for (int nt = 0; nt < 8; nt++) {
                    mma_bf16(C[mt][nt], a_hi[mt], b_hi[nt]);
                    mma_bf16(C[mt][nt], a_hi[mt], b_lo[nt]);
                    mma_bf16(C[mt][nt], a_lo[mt], b_hi[nt]);
                }
        }
    }

    // epilogue: bias add, split to bf16 hi/lo, 4B stores
    #pragma unroll
    for (int mt = 0; mt < 2; mt++) {
        const int row0 = m0 + warp_m * 32 + mt * 16 + (lane >> 2);
        #pragma unroll
        for (int nt = 0; nt < 8; nt++) {
            const int col = warp_n * 64 + nt * 8 + (lane & 3) * 2;
            float v00 = C[mt][nt][0] + sbias[col];
            float v01 = C[mt][nt][1] + sbias[col + 1];
            float v10 = C[mt][nt][2] + sbias[col];
            float v11 = C[mt][nt][3] + sbias[col + 1];
            __nv_bfloat16 h00 = __float2bfloat16(v00), h01 = __float2bfloat16(v01);
            __nv_bfloat16 h10 = __float2bfloat16(v10), h11 = __float2bfloat16(v11);
            uint32_t hi0 = pack_bf16(v00, v01), hi1 = pack_bf16(v10, v11);
            uint32_t lo0 = pack_bf16(v00 - __bfloat162float(h00), v01 - __bfloat162float(h01));
            uint32_t lo1 = pack_bf16(v10 - __bfloat162float(h10), v11 - __bfloat162float(h11));
            size_t o0 = (size_t)row0 * 1024 + col0 + col;
            size_t o1 = (size_t)(row0 + 8) * 1024 + col0 + col;
            *(uint32_t*)&OutHi[o0] = hi0;  *(uint32_t*)&OutLo[o0] = lo0;
            *(uint32_t*)&OutHi[o1] = hi1;  *(uint32_t*)&OutLo[o1] = lo1;
        }
    }
}

// ---------------------------------------------------------------------------
// V -> V^T (per b, head): [s 4096][d 64] -> [d 64][s 4096], bf16 hi and lo.
// ---------------------------------------------------------------------------
__global__ __launch_bounds__(256) void cvt_vt() {
    __shared__ __nv_bfloat16 th[64][72];
    __shared__ __nv_bfloat16 tl[64][72];
    const int s0 = blockIdx.x * 64, head = blockIdx.y, b = blockIdx.z;
    const int t = threadIdx.x;
    const __nv_bfloat16* Vh = g_Ohi + 2ull * MH;
    const __nv_bfloat16* Vl = g_Olo + 2ull * MH;
    for (int i = t; i < 64 * 64; i += 256) {
        int r = i >> 6, d = i & 63;
        size_t src = (size_t)(b * 4096 + s0 + r) * 1024 + head * 64 + d;
        th[r][d] = Vh[src];
        tl[r][d] = Vl[src];
    }
    __syncthreads();
    for (int i = t; i < 64 * 64; i += 256) {
        int d = i >> 6, r = i & 63;
        size_t dst = ((size_t)(b * 16 + head) * 64 + d) * 4096 + s0 + r;
        g_VThi[dst] = th[r][d];
        g_VTlo[dst] = tl[r][d];
    }
}

// ---------------------------------------------------------------------------
// Tensor-core block-local attention with permuted K/V groups.
// CTA = (64-row q tile, group g, batch b), 256 threads = 8 warps (4m x 2n).
// smem: Qhi 8K | Qlo 8K | Khi 32K | Klo 32K | VThi 32K | VTlo 32K = 144K.
// S warp tile 16x128; P kept in registers (accum layout == A-operand layout);
// AV partials combined across warp_n pairs via smem overlay of Q.
// ---------------------------------------------------------------------------
#define SQ_HI   0
#define SQ_LO   8192
#define SK_HI   16384
#define SK_LO   49152
#define SVT_HI  81920
#define SVT_LO  114688
#define ATTN_SMEM 147456

__global__ __launch_bounds__(256) void attn_mma(
    const int* __restrict__ perm,
    float* __restrict__ out) {
    extern __shared__ __align__(128) char smem[];
    const uint32_t sb = smem_u32(smem);
    float* outbuf = (float*)smem;          // 64x64 fp32, overlays Q after logits
    __shared__ float smax[2][64];
    __shared__ float ssum[2][64];

    const int qt = blockIdx.x;             // 0..3
    const int g  = blockIdx.y;             // 0..255
    const int b  = blockIdx.z;
    const int blk = g >> 4, head = g & 15;
    const int src = perm[g];
    const int sblk = src >> 4, shead = src & 15;

    const int t = threadIdx.x, lane = t & 31, wid = t >> 5;
    const int warp_m = wid >> 1;           // 0..3 -> S rows warp_m*16
    const int warp_n = wid & 1;            // 0..1 -> S cols warp_n*128

    // ---- cp.async fills ----
    {
        const __nv_bfloat16* Qh = g_Ohi;
        const __nv_bfloat16* Ql = g_Olo;
        const int qbase = b * 4096 + blk * 256 + qt * 64;
        for (int i = t; i < 512; i += 256) {           // Q: 64 rows x 8 chunks
            int r = i >> 3, c = i & 7;
            uint32_t sw = (uint32_t)r * 128 + ((c ^ (r & 7)) * 16);
            size_t srcb = (size_t)(qbase + r) * 1024 + head * 64 + c * 8;
            CP_ASYNC16(sb + SQ_HI + sw, Qh + srcb);
            CP_ASYNC16(sb + SQ_LO + sw, Ql + srcb);
        }
        const __nv_bfloat16* Kh = g_Ohi + (size_t)MH;
        const __nv_bfloat16* Kl = g_Olo + (size_t)MH;
        const int kbase = b * 4096 + sblk * 256;
        for (int i = t; i < 2048; i += 256) {          // K: 256 rows x 8 chunks
            int r = i >> 3, c = i & 7;
            uint32_t sw = (uint32_t)r * 128 + ((c ^ (r & 7)) * 16);
            size_t srcb = (size_t)(kbase + r) * 1024 + shead * 64 + c * 8;
            CP_ASYNC16(sb + SK_HI + sw, Kh + srcb);
            CP_ASYNC16(sb + SK_LO + sw, Kl + srcb);
        }
        const size_t vtb = ((size_t)(b * 16 + shead) * 64) * 4096 + sblk * 256;
        for (int i = t; i < 2048; i += 256) {          // VT: 64 rows x 32 chunks
            int r = i >> 5, c = i & 31;
            uint32_t sw = (uint32_t)r * 512 + ((c ^ (r & 7)) * 16);
            size_t srcb = vtb + (size_t)r * 4096 + c * 8;
            CP_ASYNC16(sb + SVT_HI + sw, g_VThi + srcb);
            CP_ASYNC16(sb + SVT_LO + sw, g_VTlo + srcb);
        }
    }
    CP_COMMIT();
    CP_WAIT0();
    __syncthreads();

    // ---- logits: S(16x128 per warp) = Q . K^T, 3-term bf16 ----
    float C[16][4];
    #pragma unroll
    for (int j = 0; j < 16; j++)
        #pragma unroll
        for (int k = 0; k < 4; k++) C[j][k] = 0.0f;

    const int a_r   = warp_m * 16 + (lane & 15);
    const uint32_t a_sw = (uint32_t)a_r * 128;
    const int b_r   = ((lane >> 4) << 3) + (lane & 7);
    const int b_csel = (lane >> 3) & 1;

    #pragma unroll
    for (int kt = 0; kt < 4; kt++) {
        uint32_t aQh[4], aQl[4];
        {
            int c = 2 * kt + (lane >> 4);
            uint32_t ra = sb + a_sw + ((c ^ (a_r & 7)) * 16);
            ldsm_x4(aQh, ra + SQ_HI);
            ldsm_x4(aQl, ra + SQ_LO);
        }
        uint32_t bKh[16][2], bKl[16][2];
        #pragma unroll
        for (int p = 0; p < 8; p++) {
            int row = warp_n * 128 + p * 16 + b_r;
            int c = 2 * kt + b_csel;
            uint32_t rb = sb + (uint32_t)row * 128 + ((c ^ (row & 7)) * 16);
            uint32_t rr[4];
            ldsm_x4(rr, rb + SK_HI);
            bKh[p * 2][0] = rr[0]; bKh[p * 2][1] = rr[1];
            bKh[p * 2 + 1][0] = rr[2]; bKh[p * 2 + 1][1] = rr[3];
            ldsm_x4(rr, rb + SK_LO);
            bKl[p * 2][0] = rr[0]; bKl[p * 2][1] = rr[1];
            bKl[p * 2 + 1][0] = rr[2]; bKl[p * 2 + 1][1] = rr[3];
        }
        #pragma unroll
        for (int nt = 0; nt < 16; nt++) {
            mma_bf16(C[nt], aQh, bKh[nt]);
            mma_bf16(C[nt], aQh, bKl[nt]);
            mma_bf16(C[nt], aQl, bKh[nt]);
        }
    }

    // ---- softmax on fragments ----
    const int fr = lane >> 2;              // warp-local rows fr, fr+8
    const int gr0 = warp_m * 16 + fr;
    const int gr1 = gr0 + 8;

    float m0 = -1e30f, m1 = -1e30f;
    #pragma unroll
    for (int j = 0; j < 16; j++) {
        m0 = fmaxf(m0, fmaxf(C[j][0], C[j][1]));
        m1 = fmaxf(m1, fmaxf(C[j][2], C[j][3]));
    }
    m0 = fmaxf(m0, __shfl_xor_sync(0xffffffffu, m0, 1));
    m0 = fmaxf(m0, __shfl_xor_sync(0xffffffffu, m0, 2));
    m1 = fmaxf(m1, __shfl_xor_sync(0xffffffffu, m1, 1));
    m1 = fmaxf(m1, __shfl_xor_sync(0xffffffffu, m1, 2));
    if ((lane & 3) == 0) {
        smax[warp_n][gr0] = m0;
        smax[warp_n][gr1] = m1;
    }
    __syncthreads();
    m0 = fmaxf(smax[0][gr0], smax[1][gr0]);
    m1 = fmaxf(smax[0][gr1], smax[1][gr1]);

    float s0 = 0.0f, s1 = 0.0f;
    #pragma unroll
    for (int j = 0; j < 16; j++) {
        C[j][0] = fast_exp((C[j][0] - m0) * 0.125f);
        C[j][1] = fast_exp((C[j][1] - m0) * 0.125f);
        C[j][2] = fast_exp((C[j][2] - m1) * 0.125f);
        C[j][3] = fast_exp((C[j][3] - m1) * 0.125f);
        s0 += C[j][0] + C[j][1];
        s1 += C[j][2] + C[j][3];
    }
    s0 += __shfl_xor_sync(0xffffffffu, s0, 1);
    s0 += __shfl_xor_sync(0xffffffffu, s0, 2);
    s1 += __shfl_xor_sync(0xffffffffu, s1, 1);
    s1 += __shfl_xor_sync(0xffffffffu, s1, 2);
    if ((lane & 3) == 0) {
        ssum[warp_n][gr0] = s0;
        ssum[warp_n][gr1] = s1;
    }

    // ---- P (unnormalized) -> bf16 hi/lo A-fragments, in registers ----
    uint32_t aPh[8][4], aPl[8][4];
    #pragma unroll
    for (int kt = 0; kt < 8; kt++) {
        int j0 = 2 * kt, j1 = 2 * kt + 1;
        float v00 = C[j0][0], v01 = C[j0][1], v02 = C[j0][2], v03 = C[j0][3];
        float v10 = C[j1][0], v11 = C[j1][1], v12 = C[j1][2], v13 = C[j1][3];
        aPh[kt][0] = pack_bf16(v00, v01);
        aPh[kt][1] = pack_bf16(v02, v03);
        aPh[kt][2] = pack_bf16(v10, v11);
        aPh[kt][3] = pack_bf16(v12, v13);
        __nv_bfloat162 h;
        h = *(__nv_bfloat162*)&aPh[kt][0];
        aPl[kt][0] = pack_bf16(v00 - __bfloat162float(h.x), v01 - __bfloat162float(h.y));
        h = *(__nv_bfloat162*)&aPh[kt][1];
        aPl[kt][1] = pack_bf16(v02 - __bfloat162float(h.x), v03 - __bfloat162float(h.y));
        h = *(__nv_bfloat162*)&aPh[kt][2];
        aPl[kt][2] = pack_bf16(v10 - __bfloat162float(h.x), v11 - __bfloat162float(h.y));
        h = *(__nv_bfloat162*)&aPh[kt][3];
        aPl[kt][3] = pack_bf16(v12 - __bfloat162float(h.x), v13 - __bfloat162float(h.y));
    }

    // ---- AV: warp partial over its 128 k's ----
    float av[8][4];
    #pragma unroll
    for (int nt = 0; nt < 8; nt++)
        #pragma unroll
        for (int k = 0; k < 4; k++) av[nt][k] = 0.0f;

    #pragma unroll
    for (int kt = 0; kt < 8; kt++) {
        uint32_t bVh[8][2], bVl[8][2];
        #pragma unroll
        for (int p = 0; p < 4; p++) {
            int row = p * 16 + b_r;        // d rows
            int c = warp_n * 16 + 2 * kt + b_csel;
            uint32_t rb = sb + (uint32_t)row * 512 + ((c ^ (row & 7)) * 16);
            uint32_t rr[4];
            ldsm_x4(rr, rb + SVT_HI);
            bVh[p * 2][0] = rr[0]; bVh[p * 2][1] = rr[1];
            bVh[p * 2 + 1][0] = rr[2]; bVh[p * 2 + 1][1] = rr[3];
            ldsm_x4(rr, rb + SVT_LO);
            bVl[p * 2][0] = rr[0]; bVl[p * 2][1] = rr[1];
            bVl[p * 2 + 1][0] = rr[2]; bVl[p * 2 + 1][1] = rr[3];
        }
        #pragma unroll
        for (int nt = 0; nt < 8; nt++) {
            mma_bf16(av[nt], aPh[kt], bVh[nt]);
            mma_bf16(av[nt], aPh[kt], bVl[nt]);
            mma_bf16(av[nt], aPl[kt], bVh[nt]);
        }
    }

    // ---- combine warp_n pairs via smem overlay of Q ----
    __syncthreads();   // everyone past logits (Q reads done); ssum visible
    if (warp_n == 0) {
        #pragma unroll
        for (int nt = 0; nt < 8; nt++) {
            int col = nt * 8 + (lane & 3) * 2;
            outbuf[gr0 * 64 + col]     = av[nt][0];
            outbuf[gr0 * 64 + col + 1] = av[nt][1];
            outbuf[gr1 * 64 + col]     = av[nt][2];
            outbuf[gr1 * 64 + col + 1] = av[nt][3];
        }
    }
    __syncthreads();
    if (warp_n == 1) {
        #pragma unroll
        for (int nt = 0; nt < 8; nt++) {
            int col = nt * 8 + (lane & 3) * 2;
            outbuf[gr0 * 64 + col]     += av[nt][0];
            outbuf[gr0 * 64 + col + 1] += av[nt][1];
            outbuf[gr1 * 64 + col]     += av[nt][2];
            outbuf[gr1 * 64 + col + 1] += av[nt][3];
        }
    }
    __syncthreads();

    // ---- normalize by row sum and write ----
    const int obase = b * 4096 + blk * 256 + qt * 64;
    for (int i = t; i < 1024; i += 256) {
        int row = i >> 4, ch = i & 15;
        float inv = 1.0f / (ssum[0][row] + ssum[1][row]);
        float4 v = *(float4*)&outbuf[row * 64 + ch * 4];
        v.x *= inv; v.y *= inv; v.z *= inv; v.w *= inv;
        *(float4*)&out[((size_t)(obase + row) * 16 + head) * 64 + ch * 4] = v;
    }
}

// ---------------------------------------------------------------------------
extern "C" void kernel_launch(void* const* d_in, const int* in_sizes, int n_in,
                              void* d_out, int out_size) {
    const float* X    = (const float*)d_in[0];
    const int*   perm = (const int*)d_in[2];
    const float* Wq   = (const float*)d_in[3];
    const float* Bq   = (const float*)d_in[4];
    const float* Wk   = (const float*)d_in[5];
    const float* Bk   = (const float*)d_in[6];
    const float* Wv   = (const float*)d_in[7];
    const float* Bv   = (const float*)d_in[8];
    float* out        = (float*)d_out;
    (void)in_sizes; (void)n_in; (void)out_size;

    cudaFuncSetAttribute(qkv_gemm_mma, cudaFuncAttributeMaxDynamicSharedMemorySize, GEMM_SMEM);
    cudaFuncSetAttribute(attn_mma, cudaFuncAttributeMaxDynamicSharedMemorySize, ATTN_SMEM);

    cvt_x<<<MROWS * HIDDEN / 4 / 256, 256>>>(X);
    cvt_w<<<dim3(32, 32, 3), dim3(32, 8)>>>(Wq, Wk, Wv);

    qkv_gemm_mma<<<dim3(24, 64), 256, GEMM_SMEM>>>(Bq, Bk, Bv);

    cvt_vt<<<dim3(64, 16, 2), 256>>>();

    attn_mma<<<dim3(4, 256, 2), 256, ATTN_SMEM>>>(perm, out);
}